// round 5
// baseline (speedup 1.0000x reference)
#include <cuda_runtime.h>
#include <cuda_fp16.h>
#include <cstdint>

namespace {
constexpr int N_ROWS = 2048;
constexpr int DIM    = 256;
constexpr int NY     = 16384;          // T*Q
constexpr int NCOL   = NY + N_ROWS;    // 18432
constexpr int BM = 128, BN = 128;
constexpr int NCT   = NCOL / BN;       // 144 column tiles
constexpr int NCT_Y = NY / BN;         // 128 are y-tiles
constexpr int NRT   = N_ROWS / BM;     // 16 row tiles
constexpr int KC     = 64;             // f16 elems per smem stage (128B rows)
constexpr int NSTAGE = DIM / KC;       // 4
constexpr int RSB    = 144;            // smem row stride bytes: 128 + 16 pad
constexpr int TB     = BM * RSB;       // 18432 B per tile buffer

constexpr uint32_t OFF_B   = 2 * TB;
constexpr uint32_t OFF_GJ  = 4 * TB;          // 73728
constexpr uint32_t OFF_GI  = OFF_GJ + 512;
constexpr uint32_t OFF_CMB = OFF_GI + 512;
constexpr uint32_t SMEM_BYTES = OFF_CMB + 1024;  // 75776

constexpr float EXP_SCALE = 1.44269504088896340736f / 0.3f;  // log2(e)/TEMP
constexpr float INV_TEMP  = 1.0f / 0.3f;
}

__device__ __half g_xh[N_ROWS * DIM];   // 1 MB
__device__ __half g_yh[NY * DIM];       // 8 MB
__device__ float  g_partial[N_ROWS * NCT * 2];  // [row][ct][{tot,pos}]

__device__ __forceinline__ uint32_t smem_u32(const void* p) {
    uint32_t a;
    asm("{ .reg .u64 t; cvta.to.shared.u64 t, %1; cvt.u32.u64 %0, t; }" : "=r"(a) : "l"(p));
    return a;
}
__device__ __forceinline__ void cp16(uint32_t saddr, const void* g) {
    asm volatile("cp.async.cg.shared.global [%0], [%1], 16;" :: "r"(saddr), "l"(g));
}
__device__ __forceinline__ float fexp2(float z) {
    float r;
    asm("ex2.approx.f32 %0, %1;" : "=f"(r) : "f"(z));
    return r;
}
__device__ __forceinline__ void mma_f16(float* d, const uint32_t* a,
                                        uint32_t b0, uint32_t b1) {
    asm volatile(
        "mma.sync.aligned.m16n8k16.row.col.f32.f16.f16.f32 "
        "{%0,%1,%2,%3},{%4,%5,%6,%7},{%8,%9},{%0,%1,%2,%3};"
        : "+f"(d[0]), "+f"(d[1]), "+f"(d[2]), "+f"(d[3])
        : "r"(a[0]), "r"(a[1]), "r"(a[2]), "r"(a[3]), "r"(b0), "r"(b1));
}

// ---------------------------------------------------------------------------
// f32 -> f16 conversion of x and y into device scratch.
// ---------------------------------------------------------------------------
__global__ void __launch_bounds__(256)
convert(const float* __restrict__ x, const float* __restrict__ y) {
    const int bid = blockIdx.x;
    const float* src;
    __half* dst;
    size_t base;
    if (bid < 256) { src = x; dst = g_xh; base = (size_t)bid * 2048; }
    else           { src = y; dst = g_yh; base = (size_t)(bid - 256) * 2048; }
    const size_t i = base + (size_t)threadIdx.x * 8;
    float4 v0 = *(const float4*)(src + i);
    float4 v1 = *(const float4*)(src + i + 4);
    __half2 h0 = __floats2half2_rn(v0.x, v0.y);
    __half2 h1 = __floats2half2_rn(v0.z, v0.w);
    __half2 h2 = __floats2half2_rn(v1.x, v1.y);
    __half2 h3 = __floats2half2_rn(v1.z, v1.w);
    uint4 o;
    o.x = *(uint32_t*)&h0; o.y = *(uint32_t*)&h1;
    o.z = *(uint32_t*)&h2; o.w = *(uint32_t*)&h3;
    *(uint4*)(dst + i) = o;
}

// ---------------------------------------------------------------------------
// f16 mma.sync fused exp-GEMM with per-row (total, group-matched) reduction.
// ---------------------------------------------------------------------------
__global__ void __launch_bounds__(256, 2)
gemm_tc(const int* __restrict__ trk) {
    extern __shared__ char smem[];
    const uint32_t sbase = smem_u32(smem);
    const int tid  = threadIdx.x;
    const int wid  = tid >> 5, lid = tid & 31;
    const int wm   = wid & 3, wn = wid >> 2;      // 4 x 2 warp grid
    const int quad = lid >> 2, qi = lid & 3;
    const int ct = blockIdx.x;   // 0..143
    const int rt = blockIdx.y;   // 0..15

    int* sGJ = (int*)(smem + OFF_GJ);
    int* sGI = (int*)(smem + OFF_GI);
    if (tid < BM) {
        sGI[tid] = trk[rt * BM + tid];
        // y col group = global col % 256; tile base % 256 = (ct&1)*128
        sGJ[tid] = (ct < NCT_Y) ? ((ct & 1) * 128 + tid)
                                : trk[(ct - NCT_Y) * BN + tid];
    }

    const __half* Ab = g_xh + (size_t)rt * BM * DIM;
    const __half* Bb = (ct < NCT_Y) ? (g_yh + (size_t)ct * BN * DIM)
                                    : (g_xh + (size_t)(ct - NCT_Y) * BN * DIM);

    float acc[2][8][4];
#pragma unroll
    for (int fi = 0; fi < 2; ++fi)
#pragma unroll
        for (int nf = 0; nf < 8; ++nf)
#pragma unroll
            for (int r = 0; r < 4; ++r) acc[fi][nf][r] = 0.0f;

    // stage issue: tile = 128 rows x 8 chunks of 16B; 4 A + 4 B per thread
    auto issue_stage = [&](int s, int buf) {
#pragma unroll
        for (int i = 0; i < 4; ++i) {
            int id = tid + 256 * i;
            int r = id >> 3, q = id & 7;
            cp16(sbase + buf * TB + r * RSB + q * 16,
                 Ab + (size_t)r * DIM + s * KC + q * 8);
        }
#pragma unroll
        for (int i = 0; i < 4; ++i) {
            int id = tid + 256 * i;
            int r = id >> 3, q = id & 7;
            cp16(sbase + OFF_B + buf * TB + r * RSB + q * 16,
                 Bb + (size_t)r * DIM + s * KC + q * 8);
        }
        asm volatile("cp.async.commit_group;" ::: "memory");
    };

    issue_stage(0, 0);

    for (int s = 0; s < NSTAGE; ++s) {
        const int buf = s & 1;
        if (s + 1 < NSTAGE) {
            issue_stage(s + 1, (s + 1) & 1);
            asm volatile("cp.async.wait_group 1;" ::: "memory");
        } else {
            asm volatile("cp.async.wait_group 0;" ::: "memory");
        }
        __syncthreads();

        const char* As = smem + buf * TB;
        const char* Bs = smem + OFF_B + buf * TB;
        // per-thread fragment base addresses (byte offsets)
        const char* ap = As + (wm * 32 + quad) * RSB + 4 * qi;
        const char* bp = Bs + (wn * 64 + quad) * RSB + 4 * qi;
#pragma unroll
        for (int k = 0; k < KC / 16; ++k) {       // 4 k16-steps (32B each)
            uint32_t a[2][4];
#pragma unroll
            for (int fi = 0; fi < 2; ++fi) {
                const char* p = ap + fi * 16 * RSB + k * 32;
                a[fi][0] = *(const uint32_t*)(p);
                a[fi][1] = *(const uint32_t*)(p + 8 * RSB);
                a[fi][2] = *(const uint32_t*)(p + 16);
                a[fi][3] = *(const uint32_t*)(p + 8 * RSB + 16);
            }
#pragma unroll
            for (int nf = 0; nf < 8; ++nf) {
                const char* p = bp + nf * 8 * RSB + k * 32;
                uint32_t b0 = *(const uint32_t*)(p);
                uint32_t b1 = *(const uint32_t*)(p + 16);
                mma_f16(acc[0][nf], a[0], b0, b1);
                mma_f16(acc[1][nf], a[1], b0, b1);
            }
        }
        __syncthreads();   // protect buf reuse at next issue
    }

    // ---- epilogue: exp + group-matched row sums, straight from fragments.
    float2* CMB = (float2*)(smem + OFF_CMB);
#pragma unroll
    for (int fi = 0; fi < 2; ++fi) {
        const int r0 = wm * 32 + fi * 16 + quad;
        const int r1 = r0 + 8;
        const int gi0 = sGI[r0], gi1 = sGI[r1];
        float t0 = 0.f, p0 = 0.f, t1 = 0.f, p1 = 0.f;
#pragma unroll
        for (int nf = 0; nf < 8; ++nf) {
            const int c0 = wn * 64 + nf * 8 + 2 * qi;
            const int gj0 = sGJ[c0], gj1 = sGJ[c0 + 1];
            float e;
            e = fexp2(acc[fi][nf][0] * EXP_SCALE); t0 += e; if (gj0 == gi0) p0 += e;
            e = fexp2(acc[fi][nf][1] * EXP_SCALE); t0 += e; if (gj1 == gi0) p0 += e;
            e = fexp2(acc[fi][nf][2] * EXP_SCALE); t1 += e; if (gj0 == gi1) p1 += e;
            e = fexp2(acc[fi][nf][3] * EXP_SCALE); t1 += e; if (gj1 == gi1) p1 += e;
        }
#pragma unroll
        for (int o = 1; o <= 2; o <<= 1) {
            t0 += __shfl_xor_sync(0xffffffffu, t0, o);
            p0 += __shfl_xor_sync(0xffffffffu, p0, o);
            t1 += __shfl_xor_sync(0xffffffffu, t1, o);
            p1 += __shfl_xor_sync(0xffffffffu, p1, o);
        }
        if (qi == 0 && wn == 1) {
            CMB[r0] = make_float2(t0, p0);
            CMB[r1] = make_float2(t1, p1);
        }
        if (fi == 0) { acc[0][0][0] = t0; acc[0][0][1] = p0; acc[0][0][2] = t1; acc[0][0][3] = p1; }
        else         { acc[1][0][0] = t0; acc[1][0][1] = p0; acc[1][0][2] = t1; acc[1][0][3] = p1; }
    }
    __syncthreads();
    if (qi == 0 && wn == 0) {
#pragma unroll
        for (int fi = 0; fi < 2; ++fi) {
            const int r0 = wm * 32 + fi * 16 + quad;
            const int r1 = r0 + 8;
            float2 o0 = CMB[r0], o1 = CMB[r1];
            float* g0 = g_partial + (((size_t)(rt * BM + r0)) * NCT + ct) * 2;
            float* g1 = g_partial + (((size_t)(rt * BM + r1)) * NCT + ct) * 2;
            g0[0] = acc[fi][0][0] + o0.x;
            g0[1] = acc[fi][0][1] + o0.y;
            g1[0] = acc[fi][0][2] + o1.x;
            g1[1] = acc[fi][0][3] + o1.y;
        }
    }
}

// ---------------------------------------------------------------------------
// Fused tail: per-row reduction over tiles + diag exclusion, then per-track
// deterministic segment sum + final loss. Single block of 1024 threads.
// ---------------------------------------------------------------------------
__global__ void __launch_bounds__(1024)
tail(const float* __restrict__ x, const int* __restrict__ trk,
     float* __restrict__ out) {
    __shared__ float snum[N_ROWS], sden[N_ROWS];
    __shared__ int   strk[N_ROWS];
    __shared__ float pnum[4][256], pden[4][256], pcnt[4][256];
    __shared__ float sl[256];
    __shared__ int   sp[256];

    const int tid = threadIdx.x;
    const int w = tid >> 5, l = tid & 31;    // 32 warps

    // Phase 1: warp-per-row reduction, 64 rows per warp.
    for (int it = 0; it < N_ROWS / 32; ++it) {
        const int row = it * 32 + w;
        float tot = 0.f, pxy = 0.f, pxx = 0.f;
        const float2* p = (const float2*)(g_partial + (size_t)row * NCT * 2);
        for (int tv = l; tv < NCT; tv += 32) {
            float2 v = p[tv];
            tot += v.x;
            if (tv < NCT_Y) pxy += v.y; else pxx += v.y;
        }
        const float4* xr = (const float4*)(x + (size_t)row * DIM);
        float sd = 0.f;
        for (int k = l; k < DIM / 4; k += 32) {
            float4 v = xr[k];
            sd += v.x * v.x + v.y * v.y + v.z * v.z + v.w * v.w;
        }
#pragma unroll
        for (int o = 16; o; o >>= 1) {
            tot += __shfl_xor_sync(0xffffffffu, tot, o);
            pxy += __shfl_xor_sync(0xffffffffu, pxy, o);
            pxx += __shfl_xor_sync(0xffffffffu, pxx, o);
            sd  += __shfl_xor_sync(0xffffffffu, sd,  o);
        }
        if (l == 0) {
            float diag = __expf(sd * INV_TEMP);
            snum[row] = pxy + 0.5f * (pxx - diag);
            sden[row] = tot - pxy - pxx;
        }
    }
    for (int r = tid; r < N_ROWS; r += 1024) strk[r] = trk[r];
    __syncthreads();

    // Phase 2: per-track segment sums, 4-way row split for parallelism.
    {
        const int t = tid & 255, q = tid >> 8;
        float num = 0.f, den = 0.f, cnt = 0.f;
        const int r0 = q * (N_ROWS / 4), r1 = r0 + N_ROWS / 4;
        for (int r = r0; r < r1; ++r) {
            if (strk[r] == t) { num += snum[r]; den += sden[r]; cnt += 1.f; }
        }
        pnum[q][t] = num; pden[q][t] = den; pcnt[q][t] = cnt;
    }
    __syncthreads();

    if (tid < 256) {
        const int t = tid;
        float num = pnum[0][t] + pnum[1][t] + pnum[2][t] + pnum[3][t];
        float den = pden[0][t] + pden[1][t] + pden[2][t] + pden[3][t];
        float cnt = pcnt[0][t] + pcnt[1][t] + pcnt[2][t] + pcnt[3][t];
        int present = (cnt > 0.f) ? 1 : 0;
        sl[t] = present ? -logf(num / (den + num)) : 0.f;
        sp[t] = present;
    }
    __syncthreads();
    for (int s = 128; s > 0; s >>= 1) {
        if (tid < s) { sl[tid] += sl[tid + s]; sp[tid] += sp[tid + s]; }
        __syncthreads();
    }
    if (tid == 0) out[0] = sl[0] / (float)sp[0];
}

// ---------------------------------------------------------------------------
extern "C" void kernel_launch(void* const* d_in, const int* in_sizes, int n_in,
                              void* d_out, int out_size) {
    const float* x   = (const float*)d_in[0];
    const int*   trk = (const int*)  d_in[1];
    const float* y   = (const float*)d_in[2];

    cudaFuncSetAttribute(gemm_tc, cudaFuncAttributeMaxDynamicSharedMemorySize,
                         (int)SMEM_BYTES);

    convert<<<256 + NY * DIM / 2048, 256>>>(x, y);
    dim3 grid(NCT, NRT);
    gemm_tc<<<grid, 256, SMEM_BYTES>>>(trk);
    tail<<<1, 1024>>>(x, trk, (float*)d_out);
}

// round 6
// speedup vs baseline: 2.2417x; 2.2417x over previous
#include <cuda_runtime.h>
#include <cuda_fp16.h>
#include <cstdint>

namespace {
constexpr int N_ROWS = 2048;
constexpr int DIM    = 256;
constexpr int NY     = 16384;          // T*Q
constexpr int NCOL   = NY + N_ROWS;    // 18432
constexpr int BM = 128, BN = 128;
constexpr int NCT   = NCOL / BN;       // 144 column tiles
constexpr int NCT_Y = NY / BN;         // 128 are y-tiles
constexpr int NRT   = N_ROWS / BM;     // 16 row tiles
constexpr int KC     = 64;             // f16 elems per smem stage (128B rows)
constexpr int NSTAGE = DIM / KC;       // 4
constexpr int RSB    = 144;            // smem row stride bytes: 128 + 16 pad
constexpr int TB     = BM * RSB;       // 18432 B per tile buffer

constexpr uint32_t OFF_B   = 2 * TB;
constexpr uint32_t OFF_GJ  = 4 * TB;          // 73728
constexpr uint32_t OFF_GI  = OFF_GJ + 512;
constexpr uint32_t OFF_CMB = OFF_GI + 512;
constexpr uint32_t SMEM_BYTES = OFF_CMB + 1024;  // 75776

constexpr float EXP_SCALE = 1.44269504088896340736f / 0.3f;  // log2(e)/TEMP
constexpr float INV_TEMP  = 1.0f / 0.3f;
}

__device__ __half g_xh[N_ROWS * DIM];   // 1 MB
__device__ __half g_yh[NY * DIM];       // 8 MB
__device__ float  g_partial[N_ROWS * NCT * 2];  // [row][ct][{tot,pos}]
__device__ float  g_rowbuf[N_ROWS * 2];         // [row][{num,den}]

__device__ __forceinline__ uint32_t smem_u32(const void* p) {
    uint32_t a;
    asm("{ .reg .u64 t; cvta.to.shared.u64 t, %1; cvt.u32.u64 %0, t; }" : "=r"(a) : "l"(p));
    return a;
}
__device__ __forceinline__ void cp16(uint32_t saddr, const void* g) {
    asm volatile("cp.async.cg.shared.global [%0], [%1], 16;" :: "r"(saddr), "l"(g));
}
__device__ __forceinline__ float fexp2(float z) {
    float r;
    asm("ex2.approx.f32 %0, %1;" : "=f"(r) : "f"(z));
    return r;
}
__device__ __forceinline__ void mma_f16(float* d, const uint32_t* a,
                                        uint32_t b0, uint32_t b1) {
    asm volatile(
        "mma.sync.aligned.m16n8k16.row.col.f32.f16.f16.f32 "
        "{%0,%1,%2,%3},{%4,%5,%6,%7},{%8,%9},{%0,%1,%2,%3};"
        : "+f"(d[0]), "+f"(d[1]), "+f"(d[2]), "+f"(d[3])
        : "r"(a[0]), "r"(a[1]), "r"(a[2]), "r"(a[3]), "r"(b0), "r"(b1));
}

// ---------------------------------------------------------------------------
// f32 -> f16 conversion of x and y into device scratch.
// ---------------------------------------------------------------------------
__global__ void __launch_bounds__(256)
convert(const float* __restrict__ x, const float* __restrict__ y) {
    const int bid = blockIdx.x;
    const float* src;
    __half* dst;
    size_t base;
    if (bid < 256) { src = x; dst = g_xh; base = (size_t)bid * 2048; }
    else           { src = y; dst = g_yh; base = (size_t)(bid - 256) * 2048; }
    const size_t i = base + (size_t)threadIdx.x * 8;
    float4 v0 = *(const float4*)(src + i);
    float4 v1 = *(const float4*)(src + i + 4);
    __half2 h0 = __floats2half2_rn(v0.x, v0.y);
    __half2 h1 = __floats2half2_rn(v0.z, v0.w);
    __half2 h2 = __floats2half2_rn(v1.x, v1.y);
    __half2 h3 = __floats2half2_rn(v1.z, v1.w);
    uint4 o;
    o.x = *(uint32_t*)&h0; o.y = *(uint32_t*)&h1;
    o.z = *(uint32_t*)&h2; o.w = *(uint32_t*)&h3;
    *(uint4*)(dst + i) = o;
}

// ---------------------------------------------------------------------------
// f16 mma.sync fused exp-GEMM with per-row (total, group-matched) reduction.
// ---------------------------------------------------------------------------
__global__ void __launch_bounds__(256, 2)
gemm_tc(const __half* __restrict__ xh, const __half* __restrict__ yh,
        const int* __restrict__ trk) {
    extern __shared__ char smem[];
    const uint32_t sbase = smem_u32(smem);
    const int tid  = threadIdx.x;
    const int wid  = tid >> 5, lid = tid & 31;
    const int wm   = wid & 3, wn = wid >> 2;      // 4 x 2 warp grid
    const int quad = lid >> 2, qi = lid & 3;
    const int ct = blockIdx.x;   // 0..143
    const int rt = blockIdx.y;   // 0..15

    int* sGJ = (int*)(smem + OFF_GJ);
    int* sGI = (int*)(smem + OFF_GI);
    if (tid < BM) {
        sGI[tid] = trk[rt * BM + tid];
        // y col group = global col % 256; tile base % 256 = (ct&1)*128
        sGJ[tid] = (ct < NCT_Y) ? ((ct & 1) * 128 + tid)
                                : trk[(ct - NCT_Y) * BN + tid];
    }

    const __half* Ab = xh + (size_t)rt * BM * DIM;
    const __half* Bb = (ct < NCT_Y) ? (yh + (size_t)ct * BN * DIM)
                                    : (xh + (size_t)(ct - NCT_Y) * BN * DIM);

    float acc[2][8][4];
#pragma unroll
    for (int fi = 0; fi < 2; ++fi)
#pragma unroll
        for (int nf = 0; nf < 8; ++nf)
#pragma unroll
            for (int r = 0; r < 4; ++r) acc[fi][nf][r] = 0.0f;

    // stage issue: tile = 128 rows x 8 chunks of 16B; 4 A + 4 B per thread
    auto issue_stage = [&](int s, int buf) {
#pragma unroll
        for (int i = 0; i < 4; ++i) {
            int id = tid + 256 * i;
            int r = id >> 3, q = id & 7;
            cp16(sbase + buf * TB + r * RSB + q * 16,
                 Ab + (size_t)r * DIM + s * KC + q * 8);
        }
#pragma unroll
        for (int i = 0; i < 4; ++i) {
            int id = tid + 256 * i;
            int r = id >> 3, q = id & 7;
            cp16(sbase + OFF_B + buf * TB + r * RSB + q * 16,
                 Bb + (size_t)r * DIM + s * KC + q * 8);
        }
        asm volatile("cp.async.commit_group;" ::: "memory");
    };

    issue_stage(0, 0);

    for (int s = 0; s < NSTAGE; ++s) {
        const int buf = s & 1;
        if (s + 1 < NSTAGE) {
            issue_stage(s + 1, (s + 1) & 1);
            asm volatile("cp.async.wait_group 1;" ::: "memory");
        } else {
            asm volatile("cp.async.wait_group 0;" ::: "memory");
        }
        __syncthreads();

        const char* As = smem + buf * TB;
        const char* Bs = smem + OFF_B + buf * TB;
        const char* ap = As + (wm * 32 + quad) * RSB + 4 * qi;
        const char* bp = Bs + (wn * 64 + quad) * RSB + 4 * qi;
#pragma unroll
        for (int k = 0; k < KC / 16; ++k) {       // 4 k16-steps (32B each)
            uint32_t a[2][4];
#pragma unroll
            for (int fi = 0; fi < 2; ++fi) {
                const char* p = ap + fi * 16 * RSB + k * 32;
                a[fi][0] = *(const uint32_t*)(p);
                a[fi][1] = *(const uint32_t*)(p + 8 * RSB);
                a[fi][2] = *(const uint32_t*)(p + 16);
                a[fi][3] = *(const uint32_t*)(p + 8 * RSB + 16);
            }
#pragma unroll
            for (int nf = 0; nf < 8; ++nf) {
                const char* p = bp + nf * 8 * RSB + k * 32;
                uint32_t b0 = *(const uint32_t*)(p);
                uint32_t b1 = *(const uint32_t*)(p + 16);
                mma_f16(acc[0][nf], a[0], b0, b1);
                mma_f16(acc[1][nf], a[1], b0, b1);
            }
        }
        __syncthreads();   // protect buf reuse at next issue
    }

    // ---- epilogue: exp + group-matched row sums, straight from fragments.
    float2* CMB = (float2*)(smem + OFF_CMB);
#pragma unroll
    for (int fi = 0; fi < 2; ++fi) {
        const int r0 = wm * 32 + fi * 16 + quad;
        const int r1 = r0 + 8;
        const int gi0 = sGI[r0], gi1 = sGI[r1];
        float t0 = 0.f, p0 = 0.f, t1 = 0.f, p1 = 0.f;
#pragma unroll
        for (int nf = 0; nf < 8; ++nf) {
            const int c0 = wn * 64 + nf * 8 + 2 * qi;
            const int gj0 = sGJ[c0], gj1 = sGJ[c0 + 1];
            float e;
            e = fexp2(acc[fi][nf][0] * EXP_SCALE); t0 += e; if (gj0 == gi0) p0 += e;
            e = fexp2(acc[fi][nf][1] * EXP_SCALE); t0 += e; if (gj1 == gi0) p0 += e;
            e = fexp2(acc[fi][nf][2] * EXP_SCALE); t1 += e; if (gj0 == gi1) p1 += e;
            e = fexp2(acc[fi][nf][3] * EXP_SCALE); t1 += e; if (gj1 == gi1) p1 += e;
        }
#pragma unroll
        for (int o = 1; o <= 2; o <<= 1) {
            t0 += __shfl_xor_sync(0xffffffffu, t0, o);
            p0 += __shfl_xor_sync(0xffffffffu, p0, o);
            t1 += __shfl_xor_sync(0xffffffffu, t1, o);
            p1 += __shfl_xor_sync(0xffffffffu, p1, o);
        }
        if (qi == 0 && wn == 1) {
            CMB[r0] = make_float2(t0, p0);
            CMB[r1] = make_float2(t1, p1);
        }
        if (fi == 0) { acc[0][0][0] = t0; acc[0][0][1] = p0; acc[0][0][2] = t1; acc[0][0][3] = p1; }
        else         { acc[1][0][0] = t0; acc[1][0][1] = p0; acc[1][0][2] = t1; acc[1][0][3] = p1; }
    }
    __syncthreads();
    if (qi == 0 && wn == 0) {
#pragma unroll
        for (int fi = 0; fi < 2; ++fi) {
            const int r0 = wm * 32 + fi * 16 + quad;
            const int r1 = r0 + 8;
            float2 o0 = CMB[r0], o1 = CMB[r1];
            float* g0 = g_partial + (((size_t)(rt * BM + r0)) * NCT + ct) * 2;
            float* g1 = g_partial + (((size_t)(rt * BM + r1)) * NCT + ct) * 2;
            g0[0] = acc[fi][0][0] + o0.x;
            g0[1] = acc[fi][0][1] + o0.y;
            g1[0] = acc[fi][0][2] + o1.x;
            g1[1] = acc[fi][0][3] + o1.y;
        }
    }
}

// ---------------------------------------------------------------------------
// Warp-per-row reduction over column tiles + diagonal exclusion (256 blocks).
// ---------------------------------------------------------------------------
__global__ void __launch_bounds__(256)
reduce_rows(const float* __restrict__ x) {
    const int row = blockIdx.x * 8 + (threadIdx.x >> 5);
    const int l = threadIdx.x & 31;

    float tot = 0.f, pxy = 0.f, pxx = 0.f;
    const float2* p = (const float2*)(g_partial + (size_t)row * NCT * 2);
#pragma unroll
    for (int tv = l; tv < NCT; tv += 32) {
        float2 v = p[tv];
        tot += v.x;
        if (tv < NCT_Y) pxy += v.y; else pxx += v.y;
    }
    const float4* xr = (const float4*)(x + (size_t)row * DIM);
    float sd = 0.f;
    for (int k = l; k < DIM / 4; k += 32) {
        float4 v = xr[k];
        sd += v.x * v.x + v.y * v.y + v.z * v.z + v.w * v.w;
    }
#pragma unroll
    for (int o = 16; o; o >>= 1) {
        tot += __shfl_xor_sync(0xffffffffu, tot, o);
        pxy += __shfl_xor_sync(0xffffffffu, pxy, o);
        pxx += __shfl_xor_sync(0xffffffffu, pxx, o);
        sd  += __shfl_xor_sync(0xffffffffu, sd,  o);
    }
    if (l == 0) {
        float diag = __expf(sd * INV_TEMP);
        g_rowbuf[row * 2 + 0] = pxy + 0.5f * (pxx - diag);
        g_rowbuf[row * 2 + 1] = tot - pxy - pxx;
    }
}

// ---------------------------------------------------------------------------
// Deterministic segment sum over tracks + final loss (1024 thr, 4-way split).
// ---------------------------------------------------------------------------
__global__ void __launch_bounds__(1024)
finalize(const int* __restrict__ trk, float* __restrict__ out) {
    __shared__ float snum[N_ROWS], sden[N_ROWS];
    __shared__ int   strk[N_ROWS];
    __shared__ float pnum[4][256], pden[4][256], pcnt[4][256];
    __shared__ float sl[256];
    __shared__ int   sp[256];

    const int tid = threadIdx.x;
    for (int r = tid; r < N_ROWS; r += 1024) {
        float2 v = *(const float2*)(g_rowbuf + 2 * r);
        snum[r] = v.x;
        sden[r] = v.y;
        strk[r] = trk[r];
    }
    __syncthreads();

    {
        const int t = tid & 255, q = tid >> 8;
        float num = 0.f, den = 0.f, cnt = 0.f;
        const int r0 = q * (N_ROWS / 4), r1 = r0 + N_ROWS / 4;
#pragma unroll 4
        for (int r = r0; r < r1; ++r) {
            if (strk[r] == t) { num += snum[r]; den += sden[r]; cnt += 1.f; }
        }
        pnum[q][t] = num; pden[q][t] = den; pcnt[q][t] = cnt;
    }
    __syncthreads();

    if (tid < 256) {
        const int t = tid;
        float num = pnum[0][t] + pnum[1][t] + pnum[2][t] + pnum[3][t];
        float den = pden[0][t] + pden[1][t] + pden[2][t] + pden[3][t];
        float cnt = pcnt[0][t] + pcnt[1][t] + pcnt[2][t] + pcnt[3][t];
        int present = (cnt > 0.f) ? 1 : 0;
        sl[t] = present ? -logf(num / (den + num)) : 0.f;
        sp[t] = present;
    }
    __syncthreads();
    for (int s = 128; s > 0; s >>= 1) {
        if (tid < s) { sl[tid] += sl[tid + s]; sp[tid] += sp[tid + s]; }
        __syncthreads();
    }
    if (tid == 0) out[0] = sl[0] / (float)sp[0];
}

// ---------------------------------------------------------------------------
extern "C" void kernel_launch(void* const* d_in, const int* in_sizes, int n_in,
                              void* d_out, int out_size) {
    const float* x   = (const float*)d_in[0];
    const int*   trk = (const int*)  d_in[1];
    const float* y   = (const float*)d_in[2];

    static __half* xh_p = nullptr;
    static __half* yh_p = nullptr;
    if (!xh_p) {
        cudaGetSymbolAddress((void**)&xh_p, g_xh);
        cudaGetSymbolAddress((void**)&yh_p, g_yh);
        cudaFuncSetAttribute(gemm_tc, cudaFuncAttributeMaxDynamicSharedMemorySize,
                             (int)SMEM_BYTES);
    }

    convert<<<256 + NY * DIM / 2048, 256>>>(x, y);
    dim3 grid(NCT, NRT);
    gemm_tc<<<grid, 256, SMEM_BYTES>>>(xh_p, yh_p, trk);
    reduce_rows<<<N_ROWS / 8, 256>>>(x);
    finalize<<<1, 1024>>>(trk, (float*)d_out);
}

// round 7
// speedup vs baseline: 2.8101x; 1.2536x over previous
#include <cuda_runtime.h>
#include <cuda_fp16.h>
#include <cstdint>

namespace {
constexpr int N_ROWS = 2048;
constexpr int DIM    = 256;
constexpr int NY     = 16384;          // T*Q
constexpr int NCOL   = NY + N_ROWS;    // 18432
constexpr int BM = 128, BN = 128;
constexpr int NCT   = NCOL / BN;       // 144 column tiles
constexpr int NCT_Y = NY / BN;         // 128 are y-tiles
constexpr int NRT   = N_ROWS / BM;     // 16 row tiles
constexpr int KC     = 64;             // f16 elems per smem stage (128B rows)
constexpr int NSTAGE = DIM / KC;       // 4
constexpr int RSB    = 144;            // smem row stride bytes: 128 + 16 pad
constexpr int TB     = BM * RSB;       // 18432 B per tile buffer

constexpr uint32_t OFF_B   = 2 * TB;
constexpr uint32_t OFF_GJ  = 4 * TB;          // 73728
constexpr uint32_t OFF_GI  = OFF_GJ + 512;
constexpr uint32_t OFF_CMB = OFF_GI + 512;
constexpr uint32_t SMEM_BYTES = OFF_CMB + 1024;  // 75776

constexpr float EXP_SCALE = 1.44269504088896340736f / 0.3f;  // log2(e)/TEMP
constexpr float INV_TEMP  = 1.0f / 0.3f;
}

__device__ __half g_xh[N_ROWS * DIM];   // 1 MB
__device__ __half g_yh[NY * DIM];       // 8 MB
__device__ float  g_partial[N_ROWS * NCT * 2];  // [row][ct][{tot,pos}]
__device__ float  g_rowbuf[N_ROWS * 2];         // [row][{num,den}]
__device__ float  g_track[512];                 // [track][{loss,present}]

__device__ __forceinline__ uint32_t smem_u32(const void* p) {
    uint32_t a;
    asm("{ .reg .u64 t; cvta.to.shared.u64 t, %1; cvt.u32.u64 %0, t; }" : "=r"(a) : "l"(p));
    return a;
}
__device__ __forceinline__ void cp16(uint32_t saddr, const void* g) {
    asm volatile("cp.async.cg.shared.global [%0], [%1], 16;" :: "r"(saddr), "l"(g));
}
__device__ __forceinline__ float fexp2(float z) {
    float r;
    asm("ex2.approx.f32 %0, %1;" : "=f"(r) : "f"(z));
    return r;
}
__device__ __forceinline__ void mma_f16(float* d, const uint32_t* a,
                                        uint32_t b0, uint32_t b1) {
    asm volatile(
        "mma.sync.aligned.m16n8k16.row.col.f32.f16.f16.f32 "
        "{%0,%1,%2,%3},{%4,%5,%6,%7},{%8,%9},{%0,%1,%2,%3};"
        : "+f"(d[0]), "+f"(d[1]), "+f"(d[2]), "+f"(d[3])
        : "r"(a[0]), "r"(a[1]), "r"(a[2]), "r"(a[3]), "r"(b0), "r"(b1));
}

// ---------------------------------------------------------------------------
// f32 -> f16 conversion of x and y into device scratch.
// ---------------------------------------------------------------------------
__global__ void __launch_bounds__(256)
convert(const float* __restrict__ x, const float* __restrict__ y) {
    const int bid = blockIdx.x;
    const float* src;
    __half* dst;
    size_t base;
    if (bid < 256) { src = x; dst = g_xh; base = (size_t)bid * 2048; }
    else           { src = y; dst = g_yh; base = (size_t)(bid - 256) * 2048; }
    const size_t i = base + (size_t)threadIdx.x * 8;
    float4 v0 = *(const float4*)(src + i);
    float4 v1 = *(const float4*)(src + i + 4);
    __half2 h0 = __floats2half2_rn(v0.x, v0.y);
    __half2 h1 = __floats2half2_rn(v0.z, v0.w);
    __half2 h2 = __floats2half2_rn(v1.x, v1.y);
    __half2 h3 = __floats2half2_rn(v1.z, v1.w);
    uint4 o;
    o.x = *(uint32_t*)&h0; o.y = *(uint32_t*)&h1;
    o.z = *(uint32_t*)&h2; o.w = *(uint32_t*)&h3;
    *(uint4*)(dst + i) = o;
}

// ---------------------------------------------------------------------------
// f16 mma.sync fused exp-GEMM with per-row (total, group-matched) reduction.
// ---------------------------------------------------------------------------
__global__ void __launch_bounds__(256, 2)
gemm_tc(const __half* __restrict__ xh, const __half* __restrict__ yh,
        const int* __restrict__ trk) {
    extern __shared__ char smem[];
    const uint32_t sbase = smem_u32(smem);
    const int tid  = threadIdx.x;
    const int wid  = tid >> 5, lid = tid & 31;
    const int wm   = wid & 3, wn = wid >> 2;      // 4 x 2 warp grid
    const int quad = lid >> 2, qi = lid & 3;
    const int ct = blockIdx.x;   // 0..143
    const int rt = blockIdx.y;   // 0..15

    int* sGJ = (int*)(smem + OFF_GJ);
    int* sGI = (int*)(smem + OFF_GI);
    if (tid < BM) {
        sGI[tid] = trk[rt * BM + tid];
        // y col group = global col % 256; tile base % 256 = (ct&1)*128
        sGJ[tid] = (ct < NCT_Y) ? ((ct & 1) * 128 + tid)
                                : trk[(ct - NCT_Y) * BN + tid];
    }

    const __half* Ab = xh + (size_t)rt * BM * DIM;
    const __half* Bb = (ct < NCT_Y) ? (yh + (size_t)ct * BN * DIM)
                                    : (xh + (size_t)(ct - NCT_Y) * BN * DIM);

    float acc[2][8][4];
#pragma unroll
    for (int fi = 0; fi < 2; ++fi)
#pragma unroll
        for (int nf = 0; nf < 8; ++nf)
#pragma unroll
            for (int r = 0; r < 4; ++r) acc[fi][nf][r] = 0.0f;

    // stage issue: tile = 128 rows x 8 chunks of 16B; 4 A + 4 B per thread
    auto issue_stage = [&](int s, int buf) {
#pragma unroll
        for (int i = 0; i < 4; ++i) {
            int id = tid + 256 * i;
            int r = id >> 3, q = id & 7;
            cp16(sbase + buf * TB + r * RSB + q * 16,
                 Ab + (size_t)r * DIM + s * KC + q * 8);
        }
#pragma unroll
        for (int i = 0; i < 4; ++i) {
            int id = tid + 256 * i;
            int r = id >> 3, q = id & 7;
            cp16(sbase + OFF_B + buf * TB + r * RSB + q * 16,
                 Bb + (size_t)r * DIM + s * KC + q * 8);
        }
        asm volatile("cp.async.commit_group;" ::: "memory");
    };

    issue_stage(0, 0);

    for (int s = 0; s < NSTAGE; ++s) {
        const int buf = s & 1;
        if (s + 1 < NSTAGE) {
            issue_stage(s + 1, (s + 1) & 1);
            asm volatile("cp.async.wait_group 1;" ::: "memory");
        } else {
            asm volatile("cp.async.wait_group 0;" ::: "memory");
        }
        __syncthreads();

        const char* As = smem + buf * TB;
        const char* Bs = smem + OFF_B + buf * TB;
        const char* ap = As + (wm * 32 + quad) * RSB + 4 * qi;
        const char* bp = Bs + (wn * 64 + quad) * RSB + 4 * qi;
#pragma unroll
        for (int k = 0; k < KC / 16; ++k) {       // 4 k16-steps (32B each)
            uint32_t a[2][4];
#pragma unroll
            for (int fi = 0; fi < 2; ++fi) {
                const char* p = ap + fi * 16 * RSB + k * 32;
                a[fi][0] = *(const uint32_t*)(p);
                a[fi][1] = *(const uint32_t*)(p + 8 * RSB);
                a[fi][2] = *(const uint32_t*)(p + 16);
                a[fi][3] = *(const uint32_t*)(p + 8 * RSB + 16);
            }
#pragma unroll
            for (int nf = 0; nf < 8; ++nf) {
                const char* p = bp + nf * 8 * RSB + k * 32;
                uint32_t b0 = *(const uint32_t*)(p);
                uint32_t b1 = *(const uint32_t*)(p + 16);
                mma_f16(acc[0][nf], a[0], b0, b1);
                mma_f16(acc[1][nf], a[1], b0, b1);
            }
        }
        __syncthreads();   // protect buf reuse at next issue
    }

    // ---- epilogue: exp + group-matched row sums, straight from fragments.
    float2* CMB = (float2*)(smem + OFF_CMB);
#pragma unroll
    for (int fi = 0; fi < 2; ++fi) {
        const int r0 = wm * 32 + fi * 16 + quad;
        const int r1 = r0 + 8;
        const int gi0 = sGI[r0], gi1 = sGI[r1];
        float t0 = 0.f, p0 = 0.f, t1 = 0.f, p1 = 0.f;
#pragma unroll
        for (int nf = 0; nf < 8; ++nf) {
            const int c0 = wn * 64 + nf * 8 + 2 * qi;
            const int gj0 = sGJ[c0], gj1 = sGJ[c0 + 1];
            float e;
            e = fexp2(acc[fi][nf][0] * EXP_SCALE); t0 += e; if (gj0 == gi0) p0 += e;
            e = fexp2(acc[fi][nf][1] * EXP_SCALE); t0 += e; if (gj1 == gi0) p0 += e;
            e = fexp2(acc[fi][nf][2] * EXP_SCALE); t1 += e; if (gj0 == gi1) p1 += e;
            e = fexp2(acc[fi][nf][3] * EXP_SCALE); t1 += e; if (gj1 == gi1) p1 += e;
        }
#pragma unroll
        for (int o = 1; o <= 2; o <<= 1) {
            t0 += __shfl_xor_sync(0xffffffffu, t0, o);
            p0 += __shfl_xor_sync(0xffffffffu, p0, o);
            t1 += __shfl_xor_sync(0xffffffffu, t1, o);
            p1 += __shfl_xor_sync(0xffffffffu, p1, o);
        }
        if (qi == 0 && wn == 1) {
            CMB[r0] = make_float2(t0, p0);
            CMB[r1] = make_float2(t1, p1);
        }
        if (fi == 0) { acc[0][0][0] = t0; acc[0][0][1] = p0; acc[0][0][2] = t1; acc[0][0][3] = p1; }
        else         { acc[1][0][0] = t0; acc[1][0][1] = p0; acc[1][0][2] = t1; acc[1][0][3] = p1; }
    }
    __syncthreads();
    if (qi == 0 && wn == 0) {
#pragma unroll
        for (int fi = 0; fi < 2; ++fi) {
            const int r0 = wm * 32 + fi * 16 + quad;
            const int r1 = r0 + 8;
            float2 o0 = CMB[r0], o1 = CMB[r1];
            float* g0 = g_partial + (((size_t)(rt * BM + r0)) * NCT + ct) * 2;
            float* g1 = g_partial + (((size_t)(rt * BM + r1)) * NCT + ct) * 2;
            g0[0] = acc[fi][0][0] + o0.x;
            g0[1] = acc[fi][0][1] + o0.y;
            g1[0] = acc[fi][0][2] + o1.x;
            g1[1] = acc[fi][0][3] + o1.y;
        }
    }
}

// ---------------------------------------------------------------------------
// Warp-per-row reduction over column tiles + diagonal exclusion (256 blocks).
// ---------------------------------------------------------------------------
__global__ void __launch_bounds__(256)
reduce_rows(const float* __restrict__ x) {
    const int row = blockIdx.x * 8 + (threadIdx.x >> 5);
    const int l = threadIdx.x & 31;

    float tot = 0.f, pxy = 0.f, pxx = 0.f;
    const float2* p = (const float2*)(g_partial + (size_t)row * NCT * 2);
#pragma unroll
    for (int tv = l; tv < NCT; tv += 32) {
        float2 v = p[tv];
        tot += v.x;
        if (tv < NCT_Y) pxy += v.y; else pxx += v.y;
    }
    const float4* xr = (const float4*)(x + (size_t)row * DIM);
    float sd = 0.f;
    for (int k = l; k < DIM / 4; k += 32) {
        float4 v = xr[k];
        sd += v.x * v.x + v.y * v.y + v.z * v.z + v.w * v.w;
    }
#pragma unroll
    for (int o = 16; o; o >>= 1) {
        tot += __shfl_xor_sync(0xffffffffu, tot, o);
        pxy += __shfl_xor_sync(0xffffffffu, pxy, o);
        pxx += __shfl_xor_sync(0xffffffffu, pxx, o);
        sd  += __shfl_xor_sync(0xffffffffu, sd,  o);
    }
    if (l == 0) {
        float diag = __expf(sd * INV_TEMP);
        g_rowbuf[row * 2 + 0] = pxy + 0.5f * (pxx - diag);
        g_rowbuf[row * 2 + 1] = tot - pxy - pxx;
    }
}

// ---------------------------------------------------------------------------
// One block per track: deterministic segment sum + per-track loss.
// ---------------------------------------------------------------------------
__global__ void __launch_bounds__(256)
track_sum(const int* __restrict__ trk) {
    const int t = blockIdx.x;            // track id
    const int tid = threadIdx.x;
    const int w = tid >> 5, l = tid & 31;

    float num = 0.f, den = 0.f, cnt = 0.f;
#pragma unroll
    for (int r = tid; r < N_ROWS; r += 256) {
        int m = (trk[r] == t);
        float2 v = *(const float2*)(g_rowbuf + 2 * r);
        if (m) { num += v.x; den += v.y; cnt += 1.f; }
    }
#pragma unroll
    for (int o = 16; o; o >>= 1) {
        num += __shfl_xor_sync(0xffffffffu, num, o);
        den += __shfl_xor_sync(0xffffffffu, den, o);
        cnt += __shfl_xor_sync(0xffffffffu, cnt, o);
    }
    __shared__ float sn[8], sd_[8], sc[8];
    if (l == 0) { sn[w] = num; sd_[w] = den; sc[w] = cnt; }
    __syncthreads();
    if (tid == 0) {
        float N = 0.f, D = 0.f, C = 0.f;
#pragma unroll
        for (int i = 0; i < 8; ++i) { N += sn[i]; D += sd_[i]; C += sc[i]; }
        int present = (C > 0.f) ? 1 : 0;
        g_track[2 * t]     = present ? -logf(N / (D + N)) : 0.f;
        g_track[2 * t + 1] = (float)present;
    }
}

// ---------------------------------------------------------------------------
// Final mean over present tracks.
// ---------------------------------------------------------------------------
__global__ void __launch_bounds__(256)
final_sum(float* __restrict__ out) {
    const int tid = threadIdx.x;
    const int w = tid >> 5, l = tid & 31;
    float2 v = *(const float2*)(g_track + 2 * tid);
    float loss = v.x, pres = v.y;
#pragma unroll
    for (int o = 16; o; o >>= 1) {
        loss += __shfl_xor_sync(0xffffffffu, loss, o);
        pres += __shfl_xor_sync(0xffffffffu, pres, o);
    }
    __shared__ float sl[8], sp[8];
    if (l == 0) { sl[w] = loss; sp[w] = pres; }
    __syncthreads();
    if (tid == 0) {
        float L = 0.f, P = 0.f;
#pragma unroll
        for (int i = 0; i < 8; ++i) { L += sl[i]; P += sp[i]; }
        out[0] = L / P;
    }
}

// ---------------------------------------------------------------------------
extern "C" void kernel_launch(void* const* d_in, const int* in_sizes, int n_in,
                              void* d_out, int out_size) {
    const float* x   = (const float*)d_in[0];
    const int*   trk = (const int*)  d_in[1];
    const float* y   = (const float*)d_in[2];

    static __half* xh_p = nullptr;
    static __half* yh_p = nullptr;
    if (!xh_p) {
        cudaGetSymbolAddress((void**)&xh_p, g_xh);
        cudaGetSymbolAddress((void**)&yh_p, g_yh);
        cudaFuncSetAttribute(gemm_tc, cudaFuncAttributeMaxDynamicSharedMemorySize,
                             (int)SMEM_BYTES);
    }

    convert<<<256 + NY * DIM / 2048, 256>>>(x, y);
    dim3 grid(NCT, NRT);
    gemm_tc<<<grid, 256, SMEM_BYTES>>>(xh_p, yh_p, trk);
    reduce_rows<<<N_ROWS / 8, 256>>>(x);
    track_sum<<<256, 256>>>(trk);
    final_sum<<<1, 256>>>((float*)d_out);
}

// round 8
// speedup vs baseline: 3.1485x; 1.1204x over previous
#include <cuda_runtime.h>
#include <cuda_fp16.h>
#include <cstdint>

namespace {
constexpr int N_ROWS = 2048;
constexpr int DIM    = 256;
constexpr int NY     = 16384;          // T*Q
constexpr int NCOL   = NY + N_ROWS;    // 18432
constexpr int BM = 128, BN = 128;
constexpr int NCT   = NCOL / BN;       // 144 column tiles
constexpr int NCT_Y = NY / BN;         // 128 are y-tiles
constexpr int NRT   = N_ROWS / BM;     // 16 row tiles
constexpr int KC     = 64;             // f16 elems per smem stage (128B rows)
constexpr int NSTAGE = DIM / KC;       // 4
constexpr int NBUF   = 3;              // cp.async pipeline depth
constexpr int RSB    = 144;            // smem row stride bytes: 128 + 16 pad
constexpr int TB     = BM * RSB;       // 18432 B per tile buffer

constexpr uint32_t OFF_B   = NBUF * TB;           // B buffers after A buffers
constexpr uint32_t OFF_GJ  = 2 * NBUF * TB;       // 110592
constexpr uint32_t OFF_GI  = OFF_GJ + 512;
constexpr uint32_t OFF_CMB = OFF_GI + 512;
constexpr uint32_t SMEM_BYTES = OFF_CMB + 1024;   // 112640 (2 CTA/SM: 225KB)

constexpr float EXP_SCALE = 1.44269504088896340736f / 0.3f;  // log2(e)/TEMP
constexpr float INV_TEMP  = 1.0f / 0.3f;
}

__device__ __half g_xh[N_ROWS * DIM];   // 1 MB
__device__ __half g_yh[NY * DIM];       // 8 MB
__device__ float  g_partial[N_ROWS * NCT * 2];  // [row][ct][{tot,pos}]
__device__ float  g_rowbuf[N_ROWS * 2];         // [row][{num,den}]
__device__ float  g_track[512];                 // [track][{loss,present}]

__device__ __forceinline__ uint32_t smem_u32(const void* p) {
    uint32_t a;
    asm("{ .reg .u64 t; cvta.to.shared.u64 t, %1; cvt.u32.u64 %0, t; }" : "=r"(a) : "l"(p));
    return a;
}
__device__ __forceinline__ void cp16(uint32_t saddr, const void* g) {
    asm volatile("cp.async.cg.shared.global [%0], [%1], 16;" :: "r"(saddr), "l"(g));
}
__device__ __forceinline__ float fexp2(float z) {
    float r;
    asm("ex2.approx.f32 %0, %1;" : "=f"(r) : "f"(z));
    return r;
}
__device__ __forceinline__ void mma_f16(float* d, const uint32_t* a,
                                        uint32_t b0, uint32_t b1) {
    asm volatile(
        "mma.sync.aligned.m16n8k16.row.col.f32.f16.f16.f32 "
        "{%0,%1,%2,%3},{%4,%5,%6,%7},{%8,%9},{%0,%1,%2,%3};"
        : "+f"(d[0]), "+f"(d[1]), "+f"(d[2]), "+f"(d[3])
        : "r"(a[0]), "r"(a[1]), "r"(a[2]), "r"(a[3]), "r"(b0), "r"(b1));
}

// ---------------------------------------------------------------------------
// f32 -> f16 conversion of x and y into device scratch.
// ---------------------------------------------------------------------------
__global__ void __launch_bounds__(256)
convert(const float* __restrict__ x, const float* __restrict__ y) {
    const int bid = blockIdx.x;
    const float* src;
    __half* dst;
    size_t base;
    if (bid < 256) { src = x; dst = g_xh; base = (size_t)bid * 2048; }
    else           { src = y; dst = g_yh; base = (size_t)(bid - 256) * 2048; }
    const size_t i = base + (size_t)threadIdx.x * 8;
    float4 v0 = *(const float4*)(src + i);
    float4 v1 = *(const float4*)(src + i + 4);
    __half2 h0 = __floats2half2_rn(v0.x, v0.y);
    __half2 h1 = __floats2half2_rn(v0.z, v0.w);
    __half2 h2 = __floats2half2_rn(v1.x, v1.y);
    __half2 h3 = __floats2half2_rn(v1.z, v1.w);
    uint4 o;
    o.x = *(uint32_t*)&h0; o.y = *(uint32_t*)&h1;
    o.z = *(uint32_t*)&h2; o.w = *(uint32_t*)&h3;
    *(uint4*)(dst + i) = o;
}

// ---------------------------------------------------------------------------
// f16 mma.sync fused exp-GEMM, 3-deep cp.async pipeline, 1 sync per stage.
// ---------------------------------------------------------------------------
__global__ void __launch_bounds__(256, 2)
gemm_tc(const __half* __restrict__ xh, const __half* __restrict__ yh,
        const int* __restrict__ trk) {
    extern __shared__ char smem[];
    const uint32_t sbase = smem_u32(smem);
    const int tid  = threadIdx.x;
    const int wid  = tid >> 5, lid = tid & 31;
    const int wm   = wid & 3, wn = wid >> 2;      // 4 x 2 warp grid
    const int quad = lid >> 2, qi = lid & 3;
    const int ct = blockIdx.x;   // 0..143
    const int rt = blockIdx.y;   // 0..15

    int* sGJ = (int*)(smem + OFF_GJ);
    int* sGI = (int*)(smem + OFF_GI);
    if (tid < BM) {
        sGI[tid] = trk[rt * BM + tid];
        // y col group = global col % 256; tile base % 256 = (ct&1)*128
        sGJ[tid] = (ct < NCT_Y) ? ((ct & 1) * 128 + tid)
                                : trk[(ct - NCT_Y) * BN + tid];
    }

    const __half* Ab = xh + (size_t)rt * BM * DIM;
    const __half* Bb = (ct < NCT_Y) ? (yh + (size_t)ct * BN * DIM)
                                    : (xh + (size_t)(ct - NCT_Y) * BN * DIM);

    float acc[2][8][4];
#pragma unroll
    for (int fi = 0; fi < 2; ++fi)
#pragma unroll
        for (int nf = 0; nf < 8; ++nf)
#pragma unroll
            for (int r = 0; r < 4; ++r) acc[fi][nf][r] = 0.0f;

    // stage issue: tile = 128 rows x 8 chunks of 16B; 4 A + 4 B per thread
    auto issue_stage = [&](int s, int buf) {
#pragma unroll
        for (int i = 0; i < 4; ++i) {
            int id = tid + 256 * i;
            int r = id >> 3, q = id & 7;
            cp16(sbase + buf * TB + r * RSB + q * 16,
                 Ab + (size_t)r * DIM + s * KC + q * 8);
        }
#pragma unroll
        for (int i = 0; i < 4; ++i) {
            int id = tid + 256 * i;
            int r = id >> 3, q = id & 7;
            cp16(sbase + OFF_B + buf * TB + r * RSB + q * 16,
                 Bb + (size_t)r * DIM + s * KC + q * 8);
        }
        asm volatile("cp.async.commit_group;" ::: "memory");
    };

    issue_stage(0, 0);
    issue_stage(1, 1);

#pragma unroll
    for (int s = 0; s < NSTAGE; ++s) {
        const int buf = s % NBUF;
        if (s < NSTAGE - 1) {
            asm volatile("cp.async.wait_group 1;" ::: "memory");
        } else {
            asm volatile("cp.async.wait_group 0;" ::: "memory");
        }
        __syncthreads();   // stage s visible to all; all readers of buf (s+2)%3 done
        if (s + 2 < NSTAGE) issue_stage(s + 2, (s + 2) % NBUF);

        const char* As = smem + buf * TB;
        const char* Bs = smem + OFF_B + buf * TB;
        const char* ap = As + (wm * 32 + quad) * RSB + 4 * qi;
        const char* bp = Bs + (wn * 64 + quad) * RSB + 4 * qi;
#pragma unroll
        for (int k = 0; k < KC / 16; ++k) {       // 4 k16-steps (32B each)
            uint32_t a[2][4];
#pragma unroll
            for (int fi = 0; fi < 2; ++fi) {
                const char* p = ap + fi * 16 * RSB + k * 32;
                a[fi][0] = *(const uint32_t*)(p);
                a[fi][1] = *(const uint32_t*)(p + 8 * RSB);
                a[fi][2] = *(const uint32_t*)(p + 16);
                a[fi][3] = *(const uint32_t*)(p + 8 * RSB + 16);
            }
#pragma unroll
            for (int nf = 0; nf < 8; ++nf) {
                const char* p = bp + nf * 8 * RSB + k * 32;
                uint32_t b0 = *(const uint32_t*)(p);
                uint32_t b1 = *(const uint32_t*)(p + 16);
                mma_f16(acc[0][nf], a[0], b0, b1);
                mma_f16(acc[1][nf], a[1], b0, b1);
            }
        }
    }

    // ---- epilogue: exp + group-matched row sums, straight from fragments.
    __syncthreads();   // mainloop fully done before CMB reuse below
    float2* CMB = (float2*)(smem + OFF_CMB);
#pragma unroll
    for (int fi = 0; fi < 2; ++fi) {
        const int r0 = wm * 32 + fi * 16 + quad;
        const int r1 = r0 + 8;
        const int gi0 = sGI[r0], gi1 = sGI[r1];
        float t0 = 0.f, p0 = 0.f, t1 = 0.f, p1 = 0.f;
#pragma unroll
        for (int nf = 0; nf < 8; ++nf) {
            const int c0 = wn * 64 + nf * 8 + 2 * qi;
            const int gj0 = sGJ[c0], gj1 = sGJ[c0 + 1];
            float e;
            e = fexp2(acc[fi][nf][0] * EXP_SCALE); t0 += e; if (gj0 == gi0) p0 += e;
            e = fexp2(acc[fi][nf][1] * EXP_SCALE); t0 += e; if (gj1 == gi0) p0 += e;
            e = fexp2(acc[fi][nf][2] * EXP_SCALE); t1 += e; if (gj0 == gi1) p1 += e;
            e = fexp2(acc[fi][nf][3] * EXP_SCALE); t1 += e; if (gj1 == gi1) p1 += e;
        }
#pragma unroll
        for (int o = 1; o <= 2; o <<= 1) {
            t0 += __shfl_xor_sync(0xffffffffu, t0, o);
            p0 += __shfl_xor_sync(0xffffffffu, p0, o);
            t1 += __shfl_xor_sync(0xffffffffu, t1, o);
            p1 += __shfl_xor_sync(0xffffffffu, p1, o);
        }
        if (qi == 0 && wn == 1) {
            CMB[r0] = make_float2(t0, p0);
            CMB[r1] = make_float2(t1, p1);
        }
        if (fi == 0) { acc[0][0][0] = t0; acc[0][0][1] = p0; acc[0][0][2] = t1; acc[0][0][3] = p1; }
        else         { acc[1][0][0] = t0; acc[1][0][1] = p0; acc[1][0][2] = t1; acc[1][0][3] = p1; }
    }
    __syncthreads();
    if (qi == 0 && wn == 0) {
#pragma unroll
        for (int fi = 0; fi < 2; ++fi) {
            const int r0 = wm * 32 + fi * 16 + quad;
            const int r1 = r0 + 8;
            float2 o0 = CMB[r0], o1 = CMB[r1];
            float* g0 = g_partial + (((size_t)(rt * BM + r0)) * NCT + ct) * 2;
            float* g1 = g_partial + (((size_t)(rt * BM + r1)) * NCT + ct) * 2;
            g0[0] = acc[fi][0][0] + o0.x;
            g0[1] = acc[fi][0][1] + o0.y;
            g1[0] = acc[fi][0][2] + o1.x;
            g1[1] = acc[fi][0][3] + o1.y;
        }
    }
}

// ---------------------------------------------------------------------------
// Warp-per-row reduction over column tiles + diagonal exclusion (256 blocks).
// ---------------------------------------------------------------------------
__global__ void __launch_bounds__(256)
reduce_rows(const float* __restrict__ x) {
    const int row = blockIdx.x * 8 + (threadIdx.x >> 5);
    const int l = threadIdx.x & 31;

    float tot = 0.f, pxy = 0.f, pxx = 0.f;
    const float2* p = (const float2*)(g_partial + (size_t)row * NCT * 2);
#pragma unroll
    for (int tv = l; tv < NCT; tv += 32) {
        float2 v = p[tv];
        tot += v.x;
        if (tv < NCT_Y) pxy += v.y; else pxx += v.y;
    }
    const float4* xr = (const float4*)(x + (size_t)row * DIM);
    float sd = 0.f;
    for (int k = l; k < DIM / 4; k += 32) {
        float4 v = xr[k];
        sd += v.x * v.x + v.y * v.y + v.z * v.z + v.w * v.w;
    }
#pragma unroll
    for (int o = 16; o; o >>= 1) {
        tot += __shfl_xor_sync(0xffffffffu, tot, o);
        pxy += __shfl_xor_sync(0xffffffffu, pxy, o);
        pxx += __shfl_xor_sync(0xffffffffu, pxx, o);
        sd  += __shfl_xor_sync(0xffffffffu, sd,  o);
    }
    if (l == 0) {
        float diag = __expf(sd * INV_TEMP);
        g_rowbuf[row * 2 + 0] = pxy + 0.5f * (pxx - diag);
        g_rowbuf[row * 2 + 1] = tot - pxy - pxx;
    }
}

// ---------------------------------------------------------------------------
// One block per track: deterministic segment sum + per-track loss.
// ---------------------------------------------------------------------------
__global__ void __launch_bounds__(256)
track_sum(const int* __restrict__ trk) {
    const int t = blockIdx.x;            // track id
    const int tid = threadIdx.x;
    const int w = tid >> 5, l = tid & 31;

    float num = 0.f, den = 0.f, cnt = 0.f;
#pragma unroll
    for (int r = tid; r < N_ROWS; r += 256) {
        int m = (trk[r] == t);
        float2 v = *(const float2*)(g_rowbuf + 2 * r);
        if (m) { num += v.x; den += v.y; cnt += 1.f; }
    }
#pragma unroll
    for (int o = 16; o; o >>= 1) {
        num += __shfl_xor_sync(0xffffffffu, num, o);
        den += __shfl_xor_sync(0xffffffffu, den, o);
        cnt += __shfl_xor_sync(0xffffffffu, cnt, o);
    }
    __shared__ float sn[8], sd_[8], sc[8];
    if (l == 0) { sn[w] = num; sd_[w] = den; sc[w] = cnt; }
    __syncthreads();
    if (tid == 0) {
        float N = 0.f, D = 0.f, C = 0.f;
#pragma unroll
        for (int i = 0; i < 8; ++i) { N += sn[i]; D += sd_[i]; C += sc[i]; }
        int present = (C > 0.f) ? 1 : 0;
        g_track[2 * t]     = present ? -logf(N / (D + N)) : 0.f;
        g_track[2 * t + 1] = (float)present;
    }
}

// ---------------------------------------------------------------------------
// Final mean over present tracks.
// ---------------------------------------------------------------------------
__global__ void __launch_bounds__(256)
final_sum(float* __restrict__ out) {
    const int tid = threadIdx.x;
    const int w = tid >> 5, l = tid & 31;
    float2 v = *(const float2*)(g_track + 2 * tid);
    float loss = v.x, pres = v.y;
#pragma unroll
    for (int o = 16; o; o >>= 1) {
        loss += __shfl_xor_sync(0xffffffffu, loss, o);
        pres += __shfl_xor_sync(0xffffffffu, pres, o);
    }
    __shared__ float sl[8], sp[8];
    if (l == 0) { sl[w] = loss; sp[w] = pres; }
    __syncthreads();
    if (tid == 0) {
        float L = 0.f, P = 0.f;
#pragma unroll
        for (int i = 0; i < 8; ++i) { L += sl[i]; P += sp[i]; }
        out[0] = L / P;
    }
}

// ---------------------------------------------------------------------------
extern "C" void kernel_launch(void* const* d_in, const int* in_sizes, int n_in,
                              void* d_out, int out_size) {
    const float* x   = (const float*)d_in[0];
    const int*   trk = (const int*)  d_in[1];
    const float* y   = (const float*)d_in[2];

    static __half* xh_p = nullptr;
    static __half* yh_p = nullptr;
    if (!xh_p) {
        cudaGetSymbolAddress((void**)&xh_p, g_xh);
        cudaGetSymbolAddress((void**)&yh_p, g_yh);
        cudaFuncSetAttribute(gemm_tc, cudaFuncAttributeMaxDynamicSharedMemorySize,
                             (int)SMEM_BYTES);
    }

    convert<<<256 + NY * DIM / 2048, 256>>>(x, y);
    dim3 grid(NCT, NRT);
    gemm_tc<<<grid, 256, SMEM_BYTES>>>(xh_p, yh_p, trk);
    reduce_rows<<<N_ROWS / 8, 256>>>(x);
    track_sum<<<256, 256>>>(trk);
    final_sum<<<1, 256>>>((float*)d_out);
}

// round 10
// speedup vs baseline: 3.3582x; 1.0666x over previous
#include <cuda_runtime.h>
#include <cuda_fp16.h>
#include <cstdint>

namespace {
constexpr int N_ROWS = 2048;
constexpr int DIM    = 256;
constexpr int NY     = 16384;          // T*Q
constexpr int NCOL   = NY + N_ROWS;    // 18432
constexpr int BM = 128, BN = 128;
constexpr int NCT   = NCOL / BN;       // 144 column tiles
constexpr int NCT_Y = NY / BN;         // 128 are y-tiles
constexpr int NRT   = N_ROWS / BM;     // 16 row tiles
constexpr int KC     = 64;             // f16 elems per smem stage (128B rows)
constexpr int NSTAGE = DIM / KC;       // 4
constexpr int NBUF   = 3;              // cp.async pipeline depth
constexpr int RSB    = 144;            // smem row stride bytes: 128 + 16 pad
constexpr int TB     = BM * RSB;       // 18432 B per tile buffer

constexpr uint32_t OFF_B   = NBUF * TB;           // B buffers after A buffers
constexpr uint32_t OFF_GJ  = 2 * NBUF * TB;       // 110592
constexpr uint32_t OFF_GI  = OFF_GJ + 512;
constexpr uint32_t OFF_CMB = OFF_GI + 512;
constexpr uint32_t SMEM_BYTES = OFF_CMB + 1024;   // 112640 (2 CTA/SM: 225KB)

constexpr float EXP_SCALE = 1.44269504088896340736f / 0.3f;  // log2(e)/TEMP
constexpr float INV_TEMP  = 1.0f / 0.3f;
}

__device__ __half g_xh[N_ROWS * DIM];   // 1 MB
__device__ __half g_yh[NY * DIM];       // 8 MB
__device__ float  g_partial[N_ROWS * NCT * 2];  // [row][ct][{tot,pos}]
__device__ float  g_rowbuf[N_ROWS * 2];         // [row][{num,den}]
__device__ float  g_track[512];                 // [track][{loss,present}]

__device__ __forceinline__ uint32_t smem_u32(const void* p) {
    uint32_t a;
    asm("{ .reg .u64 t; cvta.to.shared.u64 t, %1; cvt.u32.u64 %0, t; }" : "=r"(a) : "l"(p));
    return a;
}
__device__ __forceinline__ void cp16(uint32_t saddr, const void* g) {
    asm volatile("cp.async.cg.shared.global [%0], [%1], 16;" :: "r"(saddr), "l"(g));
}
__device__ __forceinline__ float fexp2(float z) {
    float r;
    asm("ex2.approx.f32 %0, %1;" : "=f"(r) : "f"(z));
    return r;
}
__device__ __forceinline__ void ldsm4(uint32_t* r, uint32_t addr) {
    asm volatile("ldmatrix.sync.aligned.m8n8.x4.shared.b16 {%0,%1,%2,%3}, [%4];"
        : "=r"(r[0]), "=r"(r[1]), "=r"(r[2]), "=r"(r[3]) : "r"(addr));
}
__device__ __forceinline__ void mma_f16(float* d, const uint32_t* a,
                                        uint32_t b0, uint32_t b1) {
    asm volatile(
        "mma.sync.aligned.m16n8k16.row.col.f32.f16.f16.f32 "
        "{%0,%1,%2,%3},{%4,%5,%6,%7},{%8,%9},{%0,%1,%2,%3};"
        : "+f"(d[0]), "+f"(d[1]), "+f"(d[2]), "+f"(d[3])
        : "r"(a[0]), "r"(a[1]), "r"(a[2]), "r"(a[3]), "r"(b0), "r"(b1));
}

// ---------------------------------------------------------------------------
// f32 -> f16 conversion of x and y into device scratch.
// ---------------------------------------------------------------------------
__global__ void __launch_bounds__(256)
convert(const float* __restrict__ x, const float* __restrict__ y) {
    const int bid = blockIdx.x;
    const float* src;
    __half* dst;
    size_t base;
    if (bid < 256) { src = x; dst = g_xh; base = (size_t)bid * 2048; }
    else           { src = y; dst = g_yh; base = (size_t)(bid - 256) * 2048; }
    const size_t i = base + (size_t)threadIdx.x * 8;
    float4 v0 = *(const float4*)(src + i);
    float4 v1 = *(const float4*)(src + i + 4);
    __half2 h0 = __floats2half2_rn(v0.x, v0.y);
    __half2 h1 = __floats2half2_rn(v0.z, v0.w);
    __half2 h2 = __floats2half2_rn(v1.x, v1.y);
    __half2 h3 = __floats2half2_rn(v1.z, v1.w);
    uint4 o;
    o.x = *(uint32_t*)&h0; o.y = *(uint32_t*)&h1;
    o.z = *(uint32_t*)&h2; o.w = *(uint32_t*)&h3;
    *(uint4*)(dst + i) = o;
}

// ---------------------------------------------------------------------------
// f16 mma.sync fused exp-GEMM; ldmatrix fragment loads; 3-deep cp.async pipe.
// ---------------------------------------------------------------------------
__global__ void __launch_bounds__(256, 2)
gemm_tc(const __half* __restrict__ xh, const __half* __restrict__ yh,
        const int* __restrict__ trk) {
    extern __shared__ char smem[];
    const uint32_t sbase = smem_u32(smem);
    const int tid  = threadIdx.x;
    const int wid  = tid >> 5, lid = tid & 31;
    const int wm   = wid & 3, wn = wid >> 2;      // 4 x 2 warp grid
    const int quad = lid >> 2, qi = lid & 3;
    const int g    = lid >> 3, rr = lid & 7;      // ldmatrix lane groups
    const int ct = blockIdx.x;   // 0..143
    const int rt = blockIdx.y;   // 0..15

    int* sGJ = (int*)(smem + OFF_GJ);
    int* sGI = (int*)(smem + OFF_GI);
    if (tid < BM) {
        sGI[tid] = trk[rt * BM + tid];
        // y col group = global col % 256; tile base % 256 = (ct&1)*128
        sGJ[tid] = (ct < NCT_Y) ? ((ct & 1) * 128 + tid)
                                : trk[(ct - NCT_Y) * BN + tid];
    }

    const __half* Ab = xh + (size_t)rt * BM * DIM;
    const __half* Bb = (ct < NCT_Y) ? (yh + (size_t)ct * BN * DIM)
                                    : (xh + (size_t)(ct - NCT_Y) * BN * DIM);

    float acc[2][8][4];
#pragma unroll
    for (int fi = 0; fi < 2; ++fi)
#pragma unroll
        for (int nf = 0; nf < 8; ++nf)
#pragma unroll
            for (int r = 0; r < 4; ++r) acc[fi][nf][r] = 0.0f;

    // stage issue: tile = 128 rows x 8 chunks of 16B; 4 A + 4 B per thread
    auto issue_stage = [&](int s, int buf) {
#pragma unroll
        for (int i = 0; i < 4; ++i) {
            int id = tid + 256 * i;
            int r = id >> 3, q = id & 7;
            cp16(sbase + buf * TB + r * RSB + q * 16,
                 Ab + (size_t)r * DIM + s * KC + q * 8);
        }
#pragma unroll
        for (int i = 0; i < 4; ++i) {
            int id = tid + 256 * i;
            int r = id >> 3, q = id & 7;
            cp16(sbase + OFF_B + buf * TB + r * RSB + q * 16,
                 Bb + (size_t)r * DIM + s * KC + q * 8);
        }
        asm volatile("cp.async.commit_group;" ::: "memory");
    };

    issue_stage(0, 0);
    issue_stage(1, 1);

    // per-lane ldmatrix base offsets (within a tile buffer)
    // A mats: {m0-7,k0},{m8-15,k0},{m0-7,k8},{m8-15,k8}
    const uint32_t aOff0 = (uint32_t)((wm * 32 + (g & 1) * 8 + rr) * RSB + (g >> 1) * 16);
    // B mats for pair p: {n0-7,k0},{n0-7,k8},{n8-15,k0},{n8-15,k8}
    const uint32_t bOff0 = (uint32_t)((wn * 64 + (g >> 1) * 8 + rr) * RSB + (g & 1) * 16);

#pragma unroll
    for (int s = 0; s < NSTAGE; ++s) {
        const int buf = s % NBUF;
        if (s < NSTAGE - 1) {
            asm volatile("cp.async.wait_group 1;" ::: "memory");
        } else {
            asm volatile("cp.async.wait_group 0;" ::: "memory");
        }
        __syncthreads();   // stage s visible; all readers of buf (s+2)%3 done
        if (s + 2 < NSTAGE) issue_stage(s + 2, (s + 2) % NBUF);

        const uint32_t aBase = sbase + buf * TB + aOff0;
        const uint32_t bBase = sbase + OFF_B + buf * TB + bOff0;
#pragma unroll
        for (int k = 0; k < KC / 16; ++k) {       // 4 k16-steps (32B each)
            uint32_t a[2][4];
            ldsm4(a[0], aBase + k * 32);
            ldsm4(a[1], aBase + k * 32 + 16 * RSB);
            uint32_t bb[4][4];
#pragma unroll
            for (int p = 0; p < 4; ++p)
                ldsm4(bb[p], bBase + k * 32 + p * 16 * RSB);
#pragma unroll
            for (int nf = 0; nf < 8; ++nf) {
                uint32_t b0 = bb[nf >> 1][(nf & 1) * 2];
                uint32_t b1 = bb[nf >> 1][(nf & 1) * 2 + 1];
                mma_f16(acc[0][nf], a[0], b0, b1);
                mma_f16(acc[1][nf], a[1], b0, b1);
            }
        }
    }

    // ---- epilogue: exp + group-matched row sums, straight from fragments.
    __syncthreads();   // mainloop fully done before CMB reuse below
    float2* CMB = (float2*)(smem + OFF_CMB);
#pragma unroll
    for (int fi = 0; fi < 2; ++fi) {
        const int r0 = wm * 32 + fi * 16 + quad;
        const int r1 = r0 + 8;
        const int gi0 = sGI[r0], gi1 = sGI[r1];
        float t0 = 0.f, p0 = 0.f, t1 = 0.f, p1 = 0.f;
#pragma unroll
        for (int nf = 0; nf < 8; ++nf) {
            const int c0 = wn * 64 + nf * 8 + 2 * qi;
            const int gj0 = sGJ[c0], gj1 = sGJ[c0 + 1];
            float e;
            e = fexp2(acc[fi][nf][0] * EXP_SCALE); t0 += e; if (gj0 == gi0) p0 += e;
            e = fexp2(acc[fi][nf][1] * EXP_SCALE); t0 += e; if (gj1 == gi0) p0 += e;
            e = fexp2(acc[fi][nf][2] * EXP_SCALE); t1 += e; if (gj0 == gi1) p1 += e;
            e = fexp2(acc[fi][nf][3] * EXP_SCALE); t1 += e; if (gj1 == gi1) p1 += e;
        }
#pragma unroll
        for (int o = 1; o <= 2; o <<= 1) {
            t0 += __shfl_xor_sync(0xffffffffu, t0, o);
            p0 += __shfl_xor_sync(0xffffffffu, p0, o);
            t1 += __shfl_xor_sync(0xffffffffu, t1, o);
            p1 += __shfl_xor_sync(0xffffffffu, p1, o);
        }
        if (qi == 0 && wn == 1) {
            CMB[r0] = make_float2(t0, p0);
            CMB[r1] = make_float2(t1, p1);
        }
        if (fi == 0) { acc[0][0][0] = t0; acc[0][0][1] = p0; acc[0][0][2] = t1; acc[0][0][3] = p1; }
        else         { acc[1][0][0] = t0; acc[1][0][1] = p0; acc[1][0][2] = t1; acc[1][0][3] = p1; }
    }
    __syncthreads();
    if (qi == 0 && wn == 0) {
#pragma unroll
        for (int fi = 0; fi < 2; ++fi) {
            const int r0 = wm * 32 + fi * 16 + quad;
            const int r1 = r0 + 8;
            float2 o0 = CMB[r0], o1 = CMB[r1];
            float* g0 = g_partial + (((size_t)(rt * BM + r0)) * NCT + ct) * 2;
            float* g1 = g_partial + (((size_t)(rt * BM + r1)) * NCT + ct) * 2;
            g0[0] = acc[fi][0][0] + o0.x;
            g0[1] = acc[fi][0][1] + o0.y;
            g1[0] = acc[fi][0][2] + o1.x;
            g1[1] = acc[fi][0][3] + o1.y;
        }
    }
}

// ---------------------------------------------------------------------------
// Warp-per-row reduction over column tiles + diagonal exclusion (256 blocks).
// ---------------------------------------------------------------------------
__global__ void __launch_bounds__(256)
reduce_rows(const float* __restrict__ x) {
    const int row = blockIdx.x * 8 + (threadIdx.x >> 5);
    const int l = threadIdx.x & 31;

    float tot = 0.f, pxy = 0.f, pxx = 0.f;
    const float2* p = (const float2*)(g_partial + (size_t)row * NCT * 2);
#pragma unroll
    for (int tv = l; tv < NCT; tv += 32) {
        float2 v = p[tv];
        tot += v.x;
        if (tv < NCT_Y) pxy += v.y; else pxx += v.y;
    }
    const float4* xr = (const float4*)(x + (size_t)row * DIM);
    float sd = 0.f;
    for (int k = l; k < DIM / 4; k += 32) {
        float4 v = xr[k];
        sd += v.x * v.x + v.y * v.y + v.z * v.z + v.w * v.w;
    }
#pragma unroll
    for (int o = 16; o; o >>= 1) {
        tot += __shfl_xor_sync(0xffffffffu, tot, o);
        pxy += __shfl_xor_sync(0xffffffffu, pxy, o);
        pxx += __shfl_xor_sync(0xffffffffu, pxx, o);
        sd  += __shfl_xor_sync(0xffffffffu, sd,  o);
    }
    if (l == 0) {
        float diag = __expf(sd * INV_TEMP);
        g_rowbuf[row * 2 + 0] = pxy + 0.5f * (pxx - diag);
        g_rowbuf[row * 2 + 1] = tot - pxy - pxx;
    }
}

// ---------------------------------------------------------------------------
// One block per track: deterministic segment sum + per-track loss.
// ---------------------------------------------------------------------------
__global__ void __launch_bounds__(256)
track_sum(const int* __restrict__ trk) {
    const int t = blockIdx.x;            // track id
    const int tid = threadIdx.x;
    const int w = tid >> 5, l = tid & 31;

    float num = 0.f, den = 0.f, cnt = 0.f;
#pragma unroll
    for (int r = tid; r < N_ROWS; r += 256) {
        int m = (trk[r] == t);
        float2 v = *(const float2*)(g_rowbuf + 2 * r);
        if (m) { num += v.x; den += v.y; cnt += 1.f; }
    }
#pragma unroll
    for (int o = 16; o; o >>= 1) {
        num += __shfl_xor_sync(0xffffffffu, num, o);
        den += __shfl_xor_sync(0xffffffffu, den, o);
        cnt += __shfl_xor_sync(0xffffffffu, cnt, o);
    }
    __shared__ float sn[8], sd_[8], sc[8];
    if (l == 0) { sn[w] = num; sd_[w] = den; sc[w] = cnt; }
    __syncthreads();
    if (tid == 0) {
        float N = 0.f, D = 0.f, C = 0.f;
#pragma unroll
        for (int i = 0; i < 8; ++i) { N += sn[i]; D += sd_[i]; C += sc[i]; }
        int present = (C > 0.f) ? 1 : 0;
        g_track[2 * t]     = present ? -logf(N / (D + N)) : 0.f;
        g_track[2 * t + 1] = (float)present;
    }
}

// ---------------------------------------------------------------------------
// Final mean over present tracks.
// ---------------------------------------------------------------------------
__global__ void __launch_bounds__(256)
final_sum(float* __restrict__ out) {
    const int tid = threadIdx.x;
    const int w = tid >> 5, l = tid & 31;
    float2 v = *(const float2*)(g_track + 2 * tid);
    float loss = v.x, pres = v.y;
#pragma unroll
    for (int o = 16; o; o >>= 1) {
        loss += __shfl_xor_sync(0xffffffffu, loss, o);
        pres += __shfl_xor_sync(0xffffffffu, pres, o);
    }
    __shared__ float sl[8], sp[8];
    if (l == 0) { sl[w] = loss; sp[w] = pres; }
    __syncthreads();
    if (tid == 0) {
        float L = 0.f, P = 0.f;
#pragma unroll
        for (int i = 0; i < 8; ++i) { L += sl[i]; P += sp[i]; }
        out[0] = L / P;
    }
}

// ---------------------------------------------------------------------------
extern "C" void kernel_launch(void* const* d_in, const int* in_sizes, int n_in,
                              void* d_out, int out_size) {
    const float* x   = (const float*)d_in[0];
    const int*   trk = (const int*)  d_in[1];
    const float* y   = (const float*)d_in[2];

    static __half* xh_p = nullptr;
    static __half* yh_p = nullptr;
    if (!xh_p) {
        cudaGetSymbolAddress((void**)&xh_p, g_xh);
        cudaGetSymbolAddress((void**)&yh_p, g_yh);
        cudaFuncSetAttribute(gemm_tc, cudaFuncAttributeMaxDynamicSharedMemorySize,
                             (int)SMEM_BYTES);
    }

    convert<<<256 + NY * DIM / 2048, 256>>>(x, y);
    dim3 grid(NCT, NRT);
    gemm_tc<<<grid, 256, SMEM_BYTES>>>(xh_p, yh_p, trk);
    reduce_rows<<<N_ROWS / 8, 256>>>(x);
    track_sum<<<256, 256>>>(trk);
    final_sum<<<1, 256>>>((float*)d_out);
}